// round 7
// baseline (speedup 1.0000x reference)
#include <cuda_runtime.h>

#define BATCH 8
#define NNODES 512
#define DIM 128
#define QHALF (BATCH * NNODES * (DIM / 4))   // 131072 float4 per output half

// head result: one [DIM] log_softmax vector per batch
__device__ float4 g_ls[BATCH * (DIM / 4)];

// ---------------------------------------------------------------------------
// Kernel A: head. 8 blocks (one per batch) x 256 threads.
// Full register prefetch of W1/W2 (high regs OK here — tiny grid).
// ---------------------------------------------------------------------------
__global__ void __launch_bounds__(256) gcn_head_kernel(
    const float* __restrict__ x,      // [B, N, 2]
    const float* __restrict__ Wi,     // [2, D]
    const float* __restrict__ bi,     // [D]
    const float* __restrict__ W1,     // [D, D]
    const float* __restrict__ b1,     // [D]
    const float* __restrict__ W2,     // [D, D]
    const float* __restrict__ b2)     // [D]
{
    const int b    = blockIdx.x;
    const int t    = threadIdx.x;
    const int lane = t & 31;
    const int w    = t >> 5;

    __shared__ float sv[DIM];
    __shared__ float part[8 * DIM];

    // ---- prefetch all weights before any barrier ----
    const float4* W14 = (const float4*)W1;
    const float4* W24 = (const float4*)W2;
    float4 w1r[16], w2r[16];
    #pragma unroll
    for (int kk = 0; kk < 16; kk++) w1r[kk] = W14[(w * 16 + kk) * 32 + lane];
    #pragma unroll
    for (int kk = 0; kk < 16; kk++) w2r[kk] = W24[(w * 16 + kk) * 32 + lane];

    float wi0 = 0.f, wi1 = 0.f, biv = 0.f, b1v = 0.f, b2v = 0.f;
    if (t < DIM) {
        wi0 = Wi[t]; wi1 = Wi[DIM + t];
        biv = bi[t]; b1v = b1[t]; b2v = b2[t];
    }

    const float2* xb = (const float2*)(x + (size_t)b * NNODES * 2);
    const float2 v0 = xb[t];
    const float2 v1 = xb[t + 256];

    // ---- mean of coords ----
    float s0 = v0.x + v1.x;
    float s1 = v0.y + v1.y;
    #pragma unroll
    for (int off = 16; off > 0; off >>= 1) {
        s0 += __shfl_xor_sync(0xffffffffu, s0, off);
        s1 += __shfl_xor_sync(0xffffffffu, s1, off);
    }
    if (lane == 0) { part[w] = s0; part[8 + w] = s1; }
    __syncthreads();
    const float m0 = (part[0] + part[1] + part[2] + part[3] +
                      part[4] + part[5] + part[6] + part[7]) * (1.0f / NNODES);
    const float m1 = (part[8] + part[9] + part[10] + part[11] +
                      part[12] + part[13] + part[14] + part[15]) * (1.0f / NNODES);
    __syncthreads();

    if (t < DIM) sv[t] = fmaf(m0, wi0, fmaf(m1, wi1, biv));
    __syncthreads();

    // ---- conv1 (warp-split-k) ----
    {
        float4 a = make_float4(0.f, 0.f, 0.f, 0.f);
        #pragma unroll
        for (int kk = 0; kk < 16; kk++) {
            const float s = sv[w * 16 + kk];
            a.x = fmaf(s, w1r[kk].x, a.x);
            a.y = fmaf(s, w1r[kk].y, a.y);
            a.z = fmaf(s, w1r[kk].z, a.z);
            a.w = fmaf(s, w1r[kk].w, a.w);
        }
        ((float4*)part)[w * 32 + lane] = a;
    }
    __syncthreads();
    float r1v = 0.f;
    if (t < DIM) {
        float s = b1v;
        #pragma unroll
        for (int ww = 0; ww < 8; ww++) s += part[ww * DIM + t];
        r1v = fmaxf(s, 0.f);
    }
    __syncthreads();
    if (t < DIM) sv[t] = r1v;
    __syncthreads();

    // ---- conv2 ----
    {
        float4 a = make_float4(0.f, 0.f, 0.f, 0.f);
        #pragma unroll
        for (int kk = 0; kk < 16; kk++) {
            const float s = sv[w * 16 + kk];
            a.x = fmaf(s, w2r[kk].x, a.x);
            a.y = fmaf(s, w2r[kk].y, a.y);
            a.z = fmaf(s, w2r[kk].z, a.z);
            a.w = fmaf(s, w2r[kk].w, a.w);
        }
        ((float4*)part)[w * 32 + lane] = a;
    }
    __syncthreads();
    float h = -3.402823466e+38f;
    if (t < DIM) {
        float s = b2v;
        #pragma unroll
        for (int ww = 0; ww < 8; ww++) s += part[ww * DIM + t];
        h = s;
    }
    __syncthreads();

    // ---- log_softmax over DIM ----
    float m = h;
    #pragma unroll
    for (int off = 16; off > 0; off >>= 1)
        m = fmaxf(m, __shfl_xor_sync(0xffffffffu, m, off));
    if (lane == 0) part[w] = m;
    __syncthreads();
    const float mx = fmaxf(fmaxf(part[0], part[1]), fmaxf(part[2], part[3]));

    float e = (t < DIM) ? __expf(h - mx) : 0.f;
    float se = e;
    #pragma unroll
    for (int off = 16; off > 0; off >>= 1)
        se += __shfl_xor_sync(0xffffffffu, se, off);
    __syncthreads();
    if (lane == 0) part[w] = se;
    __syncthreads();
    const float lse = __logf(part[0] + part[1] + part[2] + part[3]);

    if (t < DIM) ((float*)g_ls)[b * DIM + t] = h - mx - lse;

    // allow dependent (writer) kernel's waiting threads to proceed ASAP
    asm volatile("griddepcontrol.launch_dependents;");
}

// ---------------------------------------------------------------------------
// Kernel B: writer. 256 blocks x 256 threads; each thread writes
//   2 float4 of the node_feature half (independent of A — overlaps via PDL),
//   then waits on A, then 2 float4 of the broadcast half.
// ---------------------------------------------------------------------------
__global__ void __launch_bounds__(256) gcn_write_kernel(
    const float* __restrict__ x,
    const float* __restrict__ Wi,
    const float* __restrict__ bi,
    float* __restrict__ out)
{
    const int t    = threadIdx.x;
    const int idx0 = blockIdx.x * 512 + t;     // this thread covers idx0, idx0+256
    float4* out4 = (float4*)out;

    // d4 invariant across the +256 stride (256 % 32 == 0)
    const int d4 = idx0 & 31;
    const float4 w0 = ((const float4*)Wi)[d4];
    const float4 w1 = ((const float4*)Wi)[32 + d4];
    const float4 bb = ((const float4*)bi)[d4];

    // ---- node_feature half: out[QHALF + idx] = x @ W_init + b_init ----
    #pragma unroll
    for (int i = 0; i < 2; i++) {
        const int idx = idx0 + i * 256;
        const int b   = idx >> 14;                 // N*D/4 = 16384
        const int n   = (idx >> 5) & (NNODES - 1);
        const float2 xv = ((const float2*)x)[b * NNODES + n];
        float4 r;
        r.x = fmaf(xv.x, w0.x, fmaf(xv.y, w1.x, bb.x));
        r.y = fmaf(xv.x, w0.y, fmaf(xv.y, w1.y, bb.y));
        r.z = fmaf(xv.x, w0.z, fmaf(xv.y, w1.z, bb.z));
        r.w = fmaf(xv.x, w0.w, fmaf(xv.y, w1.w, bb.w));
        out4[QHALF + idx] = r;
    }

    // ---- broadcast half: needs A's g_ls ----
    asm volatile("griddepcontrol.wait;");
    #pragma unroll
    for (int i = 0; i < 2; i++) {
        const int idx = idx0 + i * 256;
        const int b   = idx >> 14;
        out4[idx] = g_ls[b * 32 + d4];
    }
}

extern "C" void kernel_launch(void* const* d_in, const int* in_sizes, int n_in,
                              void* d_out, int out_size) {
    const float* x  = (const float*)d_in[0];
    const float* Wi = (const float*)d_in[1];
    const float* bi = (const float*)d_in[2];
    const float* W1 = (const float*)d_in[3];
    const float* b1 = (const float*)d_in[4];
    const float* W2 = (const float*)d_in[5];
    const float* b2 = (const float*)d_in[6];
    float* out = (float*)d_out;

    gcn_head_kernel<<<BATCH, 256>>>(x, Wi, bi, W1, b1, W2, b2);

    cudaLaunchConfig_t cfg = {};
    cfg.gridDim  = dim3(QHALF / 512, 1, 1);    // 256 blocks
    cfg.blockDim = dim3(256, 1, 1);
    cfg.dynamicSmemBytes = 0;
    cfg.stream = 0;
    cudaLaunchAttribute attr[1];
    attr[0].id = cudaLaunchAttributeProgrammaticStreamSerialization;
    attr[0].val.programmaticStreamSerializationAllowed = 1;
    cfg.attrs = attr;
    cfg.numAttrs = 1;
    cudaLaunchKernelEx(&cfg, gcn_write_kernel, x, Wi, bi, out);
}

// round 14
// speedup vs baseline: 1.1991x; 1.1991x over previous
#include <cuda_runtime.h>

#define BATCH 8
#define NNODES 512
#define DIM 128
#define QHALF (BATCH * NNODES * (DIM / 4))   // 131072 float4 per output half

#define HEAD_BLOCKS 64                        // 8 per batch (redundant head compute)
#define SLICE_F4 (QHALF / HEAD_BLOCKS)        // 2048 float4 per head block

// ---------------------------------------------------------------------------
// Kernel A: head. 64 blocks (8 per batch) x 256 threads.
// Register prefetch of W1/W2 (regalloc private to this kernel).
// Each block computes the full head redundantly and writes its 32 KB slice of
// the broadcast (log_softmax) half. Signals dependents immediately so the
// independent writer kernel overlaps from the start.
// ---------------------------------------------------------------------------
__global__ void __launch_bounds__(256) gcn_head_kernel(
    const float* __restrict__ x,      // [B, N, 2]
    const float* __restrict__ Wi,     // [2, D]
    const float* __restrict__ bi,     // [D]
    const float* __restrict__ W1,     // [D, D]
    const float* __restrict__ b1,     // [D]
    const float* __restrict__ W2,     // [D, D]
    const float* __restrict__ b2,     // [D]
    float* __restrict__ out)
{
    // Writer kernel has zero data dependency on us — release it right away.
    asm volatile("griddepcontrol.launch_dependents;");

    const int b    = blockIdx.x >> 3;       // batch
    const int sub  = blockIdx.x & 7;
    const int t    = threadIdx.x;
    const int lane = t & 31;
    const int w    = t >> 5;

    __shared__ float sv[DIM];
    __shared__ float part[8 * DIM];
    __shared__ float lss[DIM];

    // ---- prefetch all weights before any barrier (MLP 32) ----
    const float4* W14 = (const float4*)W1;
    const float4* W24 = (const float4*)W2;
    float4 w1r[16], w2r[16];
    #pragma unroll
    for (int kk = 0; kk < 16; kk++) w1r[kk] = W14[(w * 16 + kk) * 32 + lane];
    #pragma unroll
    for (int kk = 0; kk < 16; kk++) w2r[kk] = W24[(w * 16 + kk) * 32 + lane];

    float wi0 = 0.f, wi1 = 0.f, biv = 0.f, b1v = 0.f, b2v = 0.f;
    if (t < DIM) {
        wi0 = Wi[t]; wi1 = Wi[DIM + t];
        biv = bi[t]; b1v = b1[t]; b2v = b2[t];
    }

    const float2* xb = (const float2*)(x + (size_t)b * NNODES * 2);
    const float2 v0 = xb[t];
    const float2 v1 = xb[t + 256];

    // ---- mean of coords ----
    float s0 = v0.x + v1.x;
    float s1 = v0.y + v1.y;
    #pragma unroll
    for (int off = 16; off > 0; off >>= 1) {
        s0 += __shfl_xor_sync(0xffffffffu, s0, off);
        s1 += __shfl_xor_sync(0xffffffffu, s1, off);
    }
    if (lane == 0) { part[w] = s0; part[8 + w] = s1; }
    __syncthreads();
    const float m0 = (part[0] + part[1] + part[2] + part[3] +
                      part[4] + part[5] + part[6] + part[7]) * (1.0f / NNODES);
    const float m1 = (part[8] + part[9] + part[10] + part[11] +
                      part[12] + part[13] + part[14] + part[15]) * (1.0f / NNODES);
    __syncthreads();

    if (t < DIM) sv[t] = fmaf(m0, wi0, fmaf(m1, wi1, biv));
    __syncthreads();

    // ---- conv1 (warp-split-k, registers) ----
    {
        float4 a = make_float4(0.f, 0.f, 0.f, 0.f);
        #pragma unroll
        for (int kk = 0; kk < 16; kk++) {
            const float s = sv[w * 16 + kk];
            a.x = fmaf(s, w1r[kk].x, a.x);
            a.y = fmaf(s, w1r[kk].y, a.y);
            a.z = fmaf(s, w1r[kk].z, a.z);
            a.w = fmaf(s, w1r[kk].w, a.w);
        }
        ((float4*)part)[w * 32 + lane] = a;
    }
    __syncthreads();
    float r1v = 0.f;
    if (t < DIM) {
        float s = b1v;
        #pragma unroll
        for (int ww = 0; ww < 8; ww++) s += part[ww * DIM + t];
        r1v = fmaxf(s, 0.f);
    }
    __syncthreads();
    if (t < DIM) sv[t] = r1v;
    __syncthreads();

    // ---- conv2 ----
    {
        float4 a = make_float4(0.f, 0.f, 0.f, 0.f);
        #pragma unroll
        for (int kk = 0; kk < 16; kk++) {
            const float s = sv[w * 16 + kk];
            a.x = fmaf(s, w2r[kk].x, a.x);
            a.y = fmaf(s, w2r[kk].y, a.y);
            a.z = fmaf(s, w2r[kk].z, a.z);
            a.w = fmaf(s, w2r[kk].w, a.w);
        }
        ((float4*)part)[w * 32 + lane] = a;
    }
    __syncthreads();
    float h = -3.402823466e+38f;
    if (t < DIM) {
        float s = b2v;
        #pragma unroll
        for (int ww = 0; ww < 8; ww++) s += part[ww * DIM + t];
        h = s;
    }
    __syncthreads();

    // ---- log_softmax over DIM ----
    float m = h;
    #pragma unroll
    for (int off = 16; off > 0; off >>= 1)
        m = fmaxf(m, __shfl_xor_sync(0xffffffffu, m, off));
    if (lane == 0) part[w] = m;
    __syncthreads();
    const float mx = fmaxf(fmaxf(part[0], part[1]), fmaxf(part[2], part[3]));

    float e = (t < DIM) ? __expf(h - mx) : 0.f;
    float se = e;
    #pragma unroll
    for (int off = 16; off > 0; off >>= 1)
        se += __shfl_xor_sync(0xffffffffu, se, off);
    __syncthreads();
    if (lane == 0) part[w] = se;
    __syncthreads();
    const float lse = __logf(part[0] + part[1] + part[2] + part[3]);

    if (t < DIM) lss[t] = h - mx - lse;
    __syncthreads();

    // ---- broadcast stores: this block's 2048-float4 slice of out[0, QHALF) ----
    const float4* ls4 = (const float4*)lss;   // 32 entries
    float4* dst = (float4*)out + (size_t)b * (NNODES * DIM / 4) + sub * SLICE_F4;
    #pragma unroll
    for (int i = 0; i < 8; i++) {
        const int pos = t + 256 * i;
        dst[pos] = ls4[pos & 31];
    }
}

// ---------------------------------------------------------------------------
// Kernel B: writer, node_feature half ONLY. 512 blocks x 256 threads, lean
// regs, high occupancy. No dependency on A — runs fully concurrent via PDL.
// ---------------------------------------------------------------------------
__global__ void __launch_bounds__(256) gcn_nf_kernel(
    const float* __restrict__ x,
    const float* __restrict__ Wi,
    const float* __restrict__ bi,
    float* __restrict__ out)
{
    const int idx = blockIdx.x * 256 + threadIdx.x;   // 0 .. QHALF-1
    float4* out4 = (float4*)out;

    const int b  = idx >> 14;                 // N*D/4 = 16384
    const int n  = (idx >> 5) & (NNODES - 1);
    const int d4 = idx & 31;
    const float2 xv = ((const float2*)x)[b * NNODES + n];
    const float4 w0 = ((const float4*)Wi)[d4];
    const float4 w1 = ((const float4*)Wi)[32 + d4];
    const float4 bb = ((const float4*)bi)[d4];
    float4 r;
    r.x = fmaf(xv.x, w0.x, fmaf(xv.y, w1.x, bb.x));
    r.y = fmaf(xv.x, w0.y, fmaf(xv.y, w1.y, bb.y));
    r.z = fmaf(xv.x, w0.z, fmaf(xv.y, w1.z, bb.z));
    r.w = fmaf(xv.x, w0.w, fmaf(xv.y, w1.w, bb.w));
    out4[QHALF + idx] = r;
}

extern "C" void kernel_launch(void* const* d_in, const int* in_sizes, int n_in,
                              void* d_out, int out_size) {
    const float* x  = (const float*)d_in[0];
    const float* Wi = (const float*)d_in[1];
    const float* bi = (const float*)d_in[2];
    const float* W1 = (const float*)d_in[3];
    const float* b1 = (const float*)d_in[4];
    const float* W2 = (const float*)d_in[5];
    const float* b2 = (const float*)d_in[6];
    float* out = (float*)d_out;

    gcn_head_kernel<<<HEAD_BLOCKS, 256>>>(x, Wi, bi, W1, b1, W2, b2, out);

    // Writer is independent of the head; PDL lets it launch as soon as all
    // head blocks have executed launch_dependents (i.e., almost immediately).
    cudaLaunchConfig_t cfg = {};
    cfg.gridDim  = dim3(QHALF / 256, 1, 1);    // 512 blocks
    cfg.blockDim = dim3(256, 1, 1);
    cfg.dynamicSmemBytes = 0;
    cfg.stream = 0;
    cudaLaunchAttribute attr[1];
    attr[0].id = cudaLaunchAttributeProgrammaticStreamSerialization;
    attr[0].val.programmaticStreamSerializationAllowed = 1;
    cfg.attrs = attr;
    cfg.numAttrs = 1;
    cudaLaunchKernelEx(&cfg, gcn_nf_kernel, x, Wi, bi, out);
}